// round 12
// baseline (speedup 1.0000x reference)
#include <cuda_runtime.h>
#include <math.h>

#define C_DIM 1280
#define HW    9216
#define WIMG  96
#define N_ID  16
#define D_IN  512
#define B_SZ  8
#define M_ROWS 128
#define KCHUNK 4

// ---------------- scratch ----------------
__device__ float g_h[M_ROWS * C_DIM];
__device__ float g_part[KCHUNK * M_ROWS * C_DIM];
__device__ float g_pt[B_SZ * C_DIM * N_ID];    // projected [b][c][n]

// ---------------- f32x2 helpers ----------------
__device__ __forceinline__ unsigned long long fma2(unsigned long long a,
                                                   unsigned long long b,
                                                   unsigned long long c) {
    unsigned long long d;
    asm("fma.rn.f32x2 %0, %1, %2, %3;" : "=l"(d) : "l"(a), "l"(b), "l"(c));
    return d;
}
__device__ __forceinline__ unsigned long long packf2(float lo, float hi) {
    unsigned long long r;
    asm("mov.b64 %0, {%1, %2};" : "=l"(r) : "f"(lo), "f"(hi));
    return r;
}
__device__ __forceinline__ float2 unpackf2(unsigned long long v) {
    float2 r;
    asm("mov.b64 {%0, %1}, %2;" : "=f"(r.x), "=f"(r.y) : "l"(v));
    return r;
}

// ---------------- mlp1: 32x32 tile f32x2 GEMM ----------------
__global__ __launch_bounds__(256) void mlp1_kernel(const float* __restrict__ E,
                                                   const float* __restrict__ W1,
                                                   const float* __restrict__ b1) {
    __shared__ float sAt[32][34];
    __shared__ float sB[32][33];
    int t = threadIdx.x, tj = t & 31, tr = t >> 5;
    int rowBase = blockIdx.y * 32, colBase = blockIdx.x * 32;
    unsigned long long acc2[2] = {0ull, 0ull};

    for (int kt = 0; kt < D_IN; kt += 32) {
#pragma unroll
        for (int s = 0; s < 4; s++) {
            int idx = t + s * 256;
            int r = idx >> 5, kk = idx & 31;
            sAt[kk][r] = E[(size_t)(rowBase + r) * D_IN + kt + kk];
            sB[r][kk]  = W1[(size_t)(kt + r) * C_DIM + colBase + kk];
        }
        __syncthreads();
#pragma unroll
        for (int k = 0; k < 32; k++) {
            float bv = sB[k][tj];
            unsigned long long bp = packf2(bv, bv);
            const unsigned long long* ap = (const unsigned long long*)&sAt[k][tr * 4];
            acc2[0] = fma2(ap[0], bp, acc2[0]);
            acc2[1] = fma2(ap[1], bp, acc2[1]);
        }
        __syncthreads();
    }
    float2 a0 = unpackf2(acc2[0]), a1 = unpackf2(acc2[1]);
    float vals[4] = {a0.x, a0.y, a1.x, a1.y};
#pragma unroll
    for (int i = 0; i < 4; i++) {
        float v = vals[i] + b1[colBase + tj];
        v = 0.5f * v * (1.f + erff(v * 0.70710678f));
        g_h[(size_t)(rowBase + tr * 4 + i) * C_DIM + colBase + tj] = v;
    }
}

// ---------------- mlp2: 64x64 tile, 16 outputs/thread, split-K=4 ----------------
__global__ __launch_bounds__(256) void mlp2_kernel(const float* __restrict__ W2) {
    __shared__ float sAt[32][68];
    __shared__ float sB[32][68];
    int t = threadIdx.x;
    int tj = t & 15;
    int tr = t >> 4;
    int rowBase = blockIdx.y * 64;
    int colBase = blockIdx.x * 64;
    int kt0 = blockIdx.z * (C_DIM / KCHUNK);
    int ktEnd = kt0 + (C_DIM / KCHUNK);

    unsigned long long acc[4][2];
#pragma unroll
    for (int i = 0; i < 4; i++) { acc[i][0] = 0ull; acc[i][1] = 0ull; }

    for (int kt = kt0; kt < ktEnd; kt += 32) {
#pragma unroll
        for (int s = 0; s < 8; s++) {
            int idx = t + s * 256;
            int r = idx >> 5, kk = idx & 31;
            sAt[kk][r] = g_h[(size_t)(rowBase + r) * C_DIM + kt + kk];
        }
#pragma unroll
        for (int s = 0; s < 8; s++) {
            int idx = t + s * 256;
            int r = idx >> 6, kk = idx & 63;
            sB[r][kk] = W2[(size_t)(kt + r) * C_DIM + colBase + kk];
        }
        __syncthreads();
#pragma unroll
        for (int k = 0; k < 32; k++) {
            float4 av = *(const float4*)&sAt[k][tr * 4];
            ulonglong2 bv = *(const ulonglong2*)&sB[k][tj * 4];
            unsigned long long a0 = packf2(av.x, av.x);
            unsigned long long a1 = packf2(av.y, av.y);
            unsigned long long a2 = packf2(av.z, av.z);
            unsigned long long a3 = packf2(av.w, av.w);
            acc[0][0] = fma2(a0, bv.x, acc[0][0]);  acc[0][1] = fma2(a0, bv.y, acc[0][1]);
            acc[1][0] = fma2(a1, bv.x, acc[1][0]);  acc[1][1] = fma2(a1, bv.y, acc[1][1]);
            acc[2][0] = fma2(a2, bv.x, acc[2][0]);  acc[2][1] = fma2(a2, bv.y, acc[2][1]);
            acc[3][0] = fma2(a3, bv.x, acc[3][0]);  acc[3][1] = fma2(a3, bv.y, acc[3][1]);
        }
        __syncthreads();
    }
    float* outp = g_part + (size_t)blockIdx.z * M_ROWS * C_DIM;
#pragma unroll
    for (int i = 0; i < 4; i++) {
        float2 v0 = unpackf2(acc[i][0]);
        float2 v1 = unpackf2(acc[i][1]);
        float4 v = make_float4(v0.x, v0.y, v1.x, v1.y);
        *(float4*)&outp[(size_t)(rowBase + tr * 4 + i) * C_DIM + colBase + tj * 4] = v;
    }
}

// ---------------- reduce split-K + bias + normalize -> g_pt[b][c][16] ----
__global__ __launch_bounds__(128) void norm_kernel(const float* __restrict__ b2v) {
    int r = blockIdx.x, t = threadIdx.x;
    int b = r >> 4, n = r & 15;
    float v[10];
    float ss = 0.f;
#pragma unroll
    for (int i = 0; i < 10; i++) {
        int c = t + i * 128;
        size_t o = (size_t)r * C_DIM + c;
        float x = b2v[c];
#pragma unroll
        for (int z = 0; z < KCHUNK; z++)
            x += g_part[o + (size_t)z * M_ROWS * C_DIM];
        v[i] = x;
        ss = fmaf(x, x, ss);
    }
#pragma unroll
    for (int o = 16; o > 0; o >>= 1) ss += __shfl_xor_sync(0xffffffffu, ss, o);
    __shared__ float sw[4];
    if ((t & 31) == 0) sw[t >> 5] = ss;
    __syncthreads();
    float tot = sw[0] + sw[1] + sw[2] + sw[3];
    float scale = 35.7770876f / (sqrtf(tot) + 1e-6f);
#pragma unroll
    for (int i = 0; i < 10; i++) {
        int c = t + i * 128;
        g_pt[((size_t)b * C_DIM + c) * N_ID + n] = v[i] * scale;
    }
}

// ---------------- fused main kernel: no smem tile, p via L1-broadcast LDG ----
// 128 thr, 1 px/thread, grid 576 (72 blk/batch), 4 CTAs/SM -> 16 warps/SM
#define UNR 8
__global__ __launch_bounds__(128, 4) void fused_kernel(const float* __restrict__ hidden,
                                                       const float* __restrict__ bboxes,
                                                       float* __restrict__ out) {
    __shared__ int sx1[N_ID], sy1[N_ID], sx2[N_ID], sy2[N_ID], semp[N_ID];

    int t = threadIdx.x;
    int blk = blockIdx.x;
    int b = blk / 72;
    int px = (blk % 72) * 128 + t;

    if (t < N_ID) {
        float bx1 = bboxes[t * 4 + 0] * 96.f;
        float by1 = bboxes[t * 4 + 1] * 96.f;
        float bx2 = bboxes[t * 4 + 2] * 96.f;
        float by2 = bboxes[t * 4 + 3] * 96.f;
        int X1 = (int)floorf(fminf(fmaxf(bx1, 0.f), 96.f));
        int Y1 = (int)floorf(fminf(fmaxf(by1, 0.f), 96.f));
        int X2 = (int)floorf(fminf(fmaxf(bx2, 0.f), 96.f));
        int Y2 = (int)floorf(fminf(fmaxf(by2, 0.f), 96.f));
        sx1[t] = X1; sy1[t] = Y1; sx2[t] = X2; sy2[t] = Y2;
        semp[t] = (X1 >= X2) || (Y1 >= Y2);
    }
    __syncthreads();

    int allempty = 1;
#pragma unroll
    for (int n = 0; n < N_ID; n++) allempty &= semp[n];

    int y = px / WIMG;
    int x = px - y * WIMG;
    const float* hp = hidden + (size_t)b * C_DIM * HW + px;
    const ulonglong2* pp = (const ulonglong2*)(g_pt + (size_t)b * C_DIM * N_ID);

    // ---- pass 1: sumsq + 16 dots; double-buffered h, p broadcast from L1 ----
    unsigned long long acc[8];
#pragma unroll
    for (int k = 0; k < 8; k++) acc[k] = 0ull;
    float ss = 0.f;

    float hA[UNR], hB[UNR];

#define LOADB(BUF, CB)                                                           \
    {                                                                            \
        _Pragma("unroll")                                                        \
        for (int i = 0; i < UNR; i++)                                            \
            BUF[i] = hp[(size_t)((CB) + i) * HW];                                \
    }
#define LOADB_G(BUF, CB)                                                         \
    if ((CB) < C_DIM) LOADB(BUF, CB)

#define P1_COMPUTE(HBUF, CB)                                                     \
    {                                                                            \
        _Pragma("unroll")                                                        \
        for (int i = 0; i < UNR; i++) {                                          \
            ss = fmaf(HBUF[i], HBUF[i], ss);                                     \
            unsigned long long hx = packf2(HBUF[i], HBUF[i]);                    \
            const ulonglong2* p4 = pp + (((CB) + i) << 2);                       \
            ulonglong2 q0 = p4[0], q1 = p4[1], q2 = p4[2], q3 = p4[3];           \
            acc[0] = fma2(hx, q0.x, acc[0]);                                     \
            acc[1] = fma2(hx, q0.y, acc[1]);                                     \
            acc[2] = fma2(hx, q1.x, acc[2]);                                     \
            acc[3] = fma2(hx, q1.y, acc[3]);                                     \
            acc[4] = fma2(hx, q2.x, acc[4]);                                     \
            acc[5] = fma2(hx, q2.y, acc[5]);                                     \
            acc[6] = fma2(hx, q3.x, acc[6]);                                     \
            acc[7] = fma2(hx, q3.y, acc[7]);                                     \
        }                                                                        \
    }

    LOADB(hA, 0)
    for (int cb = 0; cb < C_DIM; cb += 2 * UNR) {
        LOADB(hB, cb + UNR)
        P1_COMPUTE(hA, cb)
        LOADB_G(hA, cb + 2 * UNR)
        P1_COMPUTE(hB, cb + UNR)
    }

    // ---- weights ----
    const float invT = 1.999996f;               // 1/(0.5+1e-6)
    float inv = invT / (sqrtf(ss) + 1e-6f);
    float w[N_ID];
    float sum = 0.f;
#pragma unroll
    for (int k = 0; k < 8; k++) {
        float2 d = unpackf2(acc[k]);
#pragma unroll
        for (int j = 0; j < 2; j++) {
            int n = 2 * k + j;
            float dv = (j == 0) ? d.x : d.y;
            int m = allempty | ((y >= sy1[n]) & (y < sy2[n]) &
                                (x >= sx1[n]) & (x < sx2[n]));
            float s = 1.f / (1.f + __expf(-dv * inv));
            float wv = m ? s : 0.f;
            w[n] = wv;
            sum += wv;
        }
    }
    float is = 1.f / (sum + 1e-6f);
    unsigned long long wp[8];
#pragma unroll
    for (int k = 0; k < 8; k++)
        wp[k] = packf2(__powf(w[2 * k] * is, 1.2f), __powf(w[2 * k + 1] * is, 1.2f));

    // ---- pass 2: out = hidden + 1.5*sum_n w[n]*p[n,c] ----
    float* op = out + (size_t)b * C_DIM * HW + px;

#define P2_COMPUTE(HBUF, CB)                                                     \
    {                                                                            \
        _Pragma("unroll")                                                        \
        for (int i = 0; i < UNR; i++) {                                          \
            const ulonglong2* p4 = pp + (((CB) + i) << 2);                       \
            ulonglong2 q0 = p4[0], q1 = p4[1], q2 = p4[2], q3 = p4[3];           \
            unsigned long long s0 = 0ull;                                        \
            s0 = fma2(wp[0], q0.x, s0);                                          \
            s0 = fma2(wp[1], q0.y, s0);                                          \
            s0 = fma2(wp[2], q1.x, s0);                                          \
            s0 = fma2(wp[3], q1.y, s0);                                          \
            s0 = fma2(wp[4], q2.x, s0);                                          \
            s0 = fma2(wp[5], q2.y, s0);                                          \
            s0 = fma2(wp[6], q3.x, s0);                                          \
            s0 = fma2(wp[7], q3.y, s0);                                          \
            float2 a = unpackf2(s0);                                             \
            float o = fmaf(1.5f, a.x + a.y, HBUF[i]);                            \
            __stcs(op + (size_t)((CB) + i) * HW, o);                             \
        }                                                                        \
    }

    LOADB(hA, 0)
    for (int cb = 0; cb < C_DIM; cb += 2 * UNR) {
        LOADB(hB, cb + UNR)
        P2_COMPUTE(hA, cb)
        LOADB_G(hA, cb + 2 * UNR)
        P2_COMPUTE(hB, cb + UNR)
    }
}

// ---------------- launch ----------------
extern "C" void kernel_launch(void* const* d_in, const int* in_sizes, int n_in,
                              void* d_out, int out_size) {
    const float* hidden = (const float*)d_in[0];
    const float* emb    = (const float*)d_in[1];
    const float* bbox   = (const float*)d_in[2];
    const float* W1     = (const float*)d_in[3];
    const float* b1v    = (const float*)d_in[4];
    const float* W2     = (const float*)d_in[5];
    const float* b2v    = (const float*)d_in[6];
    float* outp = (float*)d_out;

    mlp1_kernel<<<dim3(C_DIM / 32, M_ROWS / 32), 256>>>(emb, W1, b1v);
    mlp2_kernel<<<dim3(C_DIM / 64, M_ROWS / 64, KCHUNK), 256>>>(W2);
    norm_kernel<<<M_ROWS, 128>>>(b2v);

    fused_kernel<<<B_SZ * 72, 128>>>(hidden, bbox, outp);
}

// round 13
// speedup vs baseline: 2.3284x; 2.3284x over previous
#include <cuda_runtime.h>
#include <math.h>

#define C_DIM 1280
#define HW    9216
#define WIMG  96
#define N_ID  16
#define D_IN  512
#define B_SZ  8
#define M_ROWS 128
#define KCHUNK 4

// ---------------- scratch ----------------
__device__ float g_h[M_ROWS * C_DIM];
__device__ float g_part[KCHUNK * M_ROWS * C_DIM];
__device__ float g_pt[B_SZ * C_DIM * N_ID];    // projected [b][c][n]

// ---------------- f32x2 helpers ----------------
__device__ __forceinline__ unsigned long long fma2(unsigned long long a,
                                                   unsigned long long b,
                                                   unsigned long long c) {
    unsigned long long d;
    asm("fma.rn.f32x2 %0, %1, %2, %3;" : "=l"(d) : "l"(a), "l"(b), "l"(c));
    return d;
}
__device__ __forceinline__ unsigned long long packf2(float lo, float hi) {
    unsigned long long r;
    asm("mov.b64 %0, {%1, %2};" : "=l"(r) : "f"(lo), "f"(hi));
    return r;
}
__device__ __forceinline__ float2 unpackf2(unsigned long long v) {
    float2 r;
    asm("mov.b64 {%0, %1}, %2;" : "=f"(r.x), "=f"(r.y) : "l"(v));
    return r;
}

// ---------------- mlp1: 32x32 tile f32x2 GEMM ----------------
__global__ __launch_bounds__(256) void mlp1_kernel(const float* __restrict__ E,
                                                   const float* __restrict__ W1,
                                                   const float* __restrict__ b1) {
    __shared__ float sAt[32][34];
    __shared__ float sB[32][33];
    int t = threadIdx.x, tj = t & 31, tr = t >> 5;
    int rowBase = blockIdx.y * 32, colBase = blockIdx.x * 32;
    unsigned long long acc2[2] = {0ull, 0ull};

    for (int kt = 0; kt < D_IN; kt += 32) {
#pragma unroll
        for (int s = 0; s < 4; s++) {
            int idx = t + s * 256;
            int r = idx >> 5, kk = idx & 31;
            sAt[kk][r] = E[(size_t)(rowBase + r) * D_IN + kt + kk];
            sB[r][kk]  = W1[(size_t)(kt + r) * C_DIM + colBase + kk];
        }
        __syncthreads();
#pragma unroll
        for (int k = 0; k < 32; k++) {
            float bv = sB[k][tj];
            unsigned long long bp = packf2(bv, bv);
            const unsigned long long* ap = (const unsigned long long*)&sAt[k][tr * 4];
            acc2[0] = fma2(ap[0], bp, acc2[0]);
            acc2[1] = fma2(ap[1], bp, acc2[1]);
        }
        __syncthreads();
    }
    float2 a0 = unpackf2(acc2[0]), a1 = unpackf2(acc2[1]);
    float vals[4] = {a0.x, a0.y, a1.x, a1.y};
#pragma unroll
    for (int i = 0; i < 4; i++) {
        float v = vals[i] + b1[colBase + tj];
        v = 0.5f * v * (1.f + erff(v * 0.70710678f));
        g_h[(size_t)(rowBase + tr * 4 + i) * C_DIM + colBase + tj] = v;
    }
}

// ---------------- mlp2: 64x64 tile, 16 outputs/thread, split-K=4 ----------------
__global__ __launch_bounds__(256) void mlp2_kernel(const float* __restrict__ W2) {
    __shared__ float sAt[32][68];
    __shared__ float sB[32][68];
    int t = threadIdx.x;
    int tj = t & 15;
    int tr = t >> 4;
    int rowBase = blockIdx.y * 64;
    int colBase = blockIdx.x * 64;
    int kt0 = blockIdx.z * (C_DIM / KCHUNK);
    int ktEnd = kt0 + (C_DIM / KCHUNK);

    unsigned long long acc[4][2];
#pragma unroll
    for (int i = 0; i < 4; i++) { acc[i][0] = 0ull; acc[i][1] = 0ull; }

    for (int kt = kt0; kt < ktEnd; kt += 32) {
#pragma unroll
        for (int s = 0; s < 8; s++) {
            int idx = t + s * 256;
            int r = idx >> 5, kk = idx & 31;
            sAt[kk][r] = g_h[(size_t)(rowBase + r) * C_DIM + kt + kk];
        }
#pragma unroll
        for (int s = 0; s < 8; s++) {
            int idx = t + s * 256;
            int r = idx >> 6, kk = idx & 63;
            sB[r][kk] = W2[(size_t)(kt + r) * C_DIM + colBase + kk];
        }
        __syncthreads();
#pragma unroll
        for (int k = 0; k < 32; k++) {
            float4 av = *(const float4*)&sAt[k][tr * 4];
            ulonglong2 bv = *(const ulonglong2*)&sB[k][tj * 4];
            unsigned long long a0 = packf2(av.x, av.x);
            unsigned long long a1 = packf2(av.y, av.y);
            unsigned long long a2 = packf2(av.z, av.z);
            unsigned long long a3 = packf2(av.w, av.w);
            acc[0][0] = fma2(a0, bv.x, acc[0][0]);  acc[0][1] = fma2(a0, bv.y, acc[0][1]);
            acc[1][0] = fma2(a1, bv.x, acc[1][0]);  acc[1][1] = fma2(a1, bv.y, acc[1][1]);
            acc[2][0] = fma2(a2, bv.x, acc[2][0]);  acc[2][1] = fma2(a2, bv.y, acc[2][1]);
            acc[3][0] = fma2(a3, bv.x, acc[3][0]);  acc[3][1] = fma2(a3, bv.y, acc[3][1]);
        }
        __syncthreads();
    }
    float* outp = g_part + (size_t)blockIdx.z * M_ROWS * C_DIM;
#pragma unroll
    for (int i = 0; i < 4; i++) {
        float2 v0 = unpackf2(acc[i][0]);
        float2 v1 = unpackf2(acc[i][1]);
        float4 v = make_float4(v0.x, v0.y, v1.x, v1.y);
        *(float4*)&outp[(size_t)(rowBase + tr * 4 + i) * C_DIM + colBase + tj * 4] = v;
    }
}

// ---------------- reduce split-K + bias + normalize -> g_pt[b][c][16] ----
__global__ __launch_bounds__(128) void norm_kernel(const float* __restrict__ b2v) {
    int r = blockIdx.x, t = threadIdx.x;
    int b = r >> 4, n = r & 15;
    float v[10];
    float ss = 0.f;
#pragma unroll
    for (int i = 0; i < 10; i++) {
        int c = t + i * 128;
        size_t o = (size_t)r * C_DIM + c;
        float x = b2v[c];
#pragma unroll
        for (int z = 0; z < KCHUNK; z++)
            x += g_part[o + (size_t)z * M_ROWS * C_DIM];
        v[i] = x;
        ss = fmaf(x, x, ss);
    }
#pragma unroll
    for (int o = 16; o > 0; o >>= 1) ss += __shfl_xor_sync(0xffffffffu, ss, o);
    __shared__ float sw[4];
    if ((t & 31) == 0) sw[t >> 5] = ss;
    __syncthreads();
    float tot = sw[0] + sw[1] + sw[2] + sw[3];
    float scale = 35.7770876f / (sqrtf(tot) + 1e-6f);
#pragma unroll
    for (int i = 0; i < 10; i++) {
        int c = t + i * 128;
        g_pt[((size_t)b * C_DIM + c) * N_ID + n] = v[i] * scale;
    }
}

// ---------------- fused main kernel (2-stage pipelined, 1 px/thread) ----------------
// 256 thr, 256 px/CTA, grid 288 (36 blk/batch), 80KB smem, 2 CTAs/SM, 16 warps/SM
#define UNR 8          // channels per batch; 2 batches in flight
__global__ __launch_bounds__(256, 2) void fused_kernel(const float* __restrict__ hidden,
                                                       const float* __restrict__ bboxes,
                                                       float* __restrict__ out) {
    extern __shared__ float sp[];               // [1280][16]
    __shared__ int sx1[N_ID], sy1[N_ID], sx2[N_ID], sy2[N_ID], semp[N_ID];

    int t = threadIdx.x;
    int blk = blockIdx.x;
    int b = blk / 36;
    int px = (blk % 36) * 256 + t;

    const float4* src = (const float4*)(g_pt + (size_t)b * C_DIM * N_ID);
    float4* dst = (float4*)sp;
#pragma unroll
    for (int i = 0; i < 20; i++) dst[t + i * 256] = src[t + i * 256];

    if (t < N_ID) {
        float bx1 = bboxes[t * 4 + 0] * 96.f;
        float by1 = bboxes[t * 4 + 1] * 96.f;
        float bx2 = bboxes[t * 4 + 2] * 96.f;
        float by2 = bboxes[t * 4 + 3] * 96.f;
        int X1 = (int)floorf(fminf(fmaxf(bx1, 0.f), 96.f));
        int Y1 = (int)floorf(fminf(fmaxf(by1, 0.f), 96.f));
        int X2 = (int)floorf(fminf(fmaxf(bx2, 0.f), 96.f));
        int Y2 = (int)floorf(fminf(fmaxf(by2, 0.f), 96.f));
        sx1[t] = X1; sy1[t] = Y1; sx2[t] = X2; sy2[t] = Y2;
        semp[t] = (X1 >= X2) || (Y1 >= Y2);
    }
    __syncthreads();

    int allempty = 1;
#pragma unroll
    for (int n = 0; n < N_ID; n++) allempty &= semp[n];

    int y = px / WIMG;
    int x = px - y * WIMG;
    const float* hp = hidden + (size_t)b * C_DIM * HW + px;

    // ---- pass 1: sumsq + 16 dots; 2-stage pipeline, scalar loads ----
    unsigned long long acc[8];
#pragma unroll
    for (int k = 0; k < 8; k++) acc[k] = 0ull;
    float ss = 0.f;

    float h0[UNR], h1[UNR];

#define LOADB(BUF, CB)                                                           \
    {                                                                            \
        _Pragma("unroll")                                                        \
        for (int i = 0; i < UNR; i++)                                            \
            BUF[i] = hp[(size_t)((CB) + i) * HW];                                \
    }
#define LOADB_G(BUF, CB)                                                         \
    if ((CB) < C_DIM) LOADB(BUF, CB)

#define P1_COMPUTE(HBUF, CB)                                                     \
    {                                                                            \
        _Pragma("unroll")                                                        \
        for (int i = 0; i < UNR; i++) {                                          \
            ss = fmaf(HBUF[i], HBUF[i], ss);                                     \
            unsigned long long hx = packf2(HBUF[i], HBUF[i]);                    \
            const ulonglong2* p2 = (const ulonglong2*)(sp + (((CB) + i) << 4));  \
            ulonglong2 q0 = p2[0], q1 = p2[1], q2 = p2[2], q3 = p2[3];           \
            acc[0] = fma2(hx, q0.x, acc[0]);                                     \
            acc[1] = fma2(hx, q0.y, acc[1]);                                     \
            acc[2] = fma2(hx, q1.x, acc[2]);                                     \
            acc[3] = fma2(hx, q1.y, acc[3]);                                     \
            acc[4] = fma2(hx, q2.x, acc[4]);                                     \
            acc[5] = fma2(hx, q2.y, acc[5]);                                     \
            acc[6] = fma2(hx, q3.x, acc[6]);                                     \
            acc[7] = fma2(hx, q3.y, acc[7]);                                     \
        }                                                                        \
    }

    LOADB(h0, 0)
    for (int cb = 0; cb < C_DIM; cb += 2 * UNR) {
        LOADB(h1, cb + UNR)
        P1_COMPUTE(h0, cb)
        LOADB_G(h0, cb + 2 * UNR)
        P1_COMPUTE(h1, cb + UNR)
    }

    // ---- weights ----
    const float invT = 1.999996f;               // 1/(0.5+1e-6)
    float inv = invT / (sqrtf(ss) + 1e-6f);
    float w[N_ID];
    float sum = 0.f;
#pragma unroll
    for (int k = 0; k < 8; k++) {
        float2 d = unpackf2(acc[k]);
#pragma unroll
        for (int j = 0; j < 2; j++) {
            int n = 2 * k + j;
            float dv = (j == 0) ? d.x : d.y;
            int m = allempty | ((y >= sy1[n]) & (y < sy2[n]) &
                                (x >= sx1[n]) & (x < sx2[n]));
            float s = 1.f / (1.f + __expf(-dv * inv));
            float wv = m ? s : 0.f;
            w[n] = wv;
            sum += wv;
        }
    }
    float is = 1.f / (sum + 1e-6f);
    unsigned long long wp[8];
#pragma unroll
    for (int k = 0; k < 8; k++)
        wp[k] = packf2(__powf(w[2 * k] * is, 1.2f), __powf(w[2 * k + 1] * is, 1.2f));

    // ---- pass 2: out = hidden + 1.5*sum_n w[n]*p[n,c]; 2-stage pipeline ----
    float* op = out + (size_t)b * C_DIM * HW + px;

#define P2_COMPUTE(HBUF, CB)                                                     \
    {                                                                            \
        _Pragma("unroll")                                                        \
        for (int i = 0; i < UNR; i++) {                                          \
            const ulonglong2* pq = (const ulonglong2*)(sp + (((CB) + i) << 4));  \
            ulonglong2 q0 = pq[0], q1 = pq[1], q2 = pq[2], q3 = pq[3];           \
            unsigned long long s0 = 0ull;                                        \
            s0 = fma2(wp[0], q0.x, s0);                                          \
            s0 = fma2(wp[1], q0.y, s0);                                          \
            s0 = fma2(wp[2], q1.x, s0);                                          \
            s0 = fma2(wp[3], q1.y, s0);                                          \
            s0 = fma2(wp[4], q2.x, s0);                                          \
            s0 = fma2(wp[5], q2.y, s0);                                          \
            s0 = fma2(wp[6], q3.x, s0);                                          \
            s0 = fma2(wp[7], q3.y, s0);                                          \
            float2 a = unpackf2(s0);                                             \
            float o = fmaf(1.5f, a.x + a.y, HBUF[i]);                            \
            __stcs(op + (size_t)((CB) + i) * HW, o);                             \
        }                                                                        \
    }

    LOADB(h0, 0)
    for (int cb = 0; cb < C_DIM; cb += 2 * UNR) {
        LOADB(h1, cb + UNR)
        P2_COMPUTE(h0, cb)
        LOADB_G(h0, cb + 2 * UNR)
        P2_COMPUTE(h1, cb + UNR)
    }
}

// ---------------- launch ----------------
extern "C" void kernel_launch(void* const* d_in, const int* in_sizes, int n_in,
                              void* d_out, int out_size) {
    const float* hidden = (const float*)d_in[0];
    const float* emb    = (const float*)d_in[1];
    const float* bbox   = (const float*)d_in[2];
    const float* W1     = (const float*)d_in[3];
    const float* b1v    = (const float*)d_in[4];
    const float* W2     = (const float*)d_in[5];
    const float* b2v    = (const float*)d_in[6];
    float* outp = (float*)d_out;

    mlp1_kernel<<<dim3(C_DIM / 32, M_ROWS / 32), 256>>>(emb, W1, b1v);
    mlp2_kernel<<<dim3(C_DIM / 64, M_ROWS / 64, KCHUNK), 256>>>(W2);
    norm_kernel<<<M_ROWS, 128>>>(b2v);

    cudaFuncSetAttribute(fused_kernel, cudaFuncAttributeMaxDynamicSharedMemorySize,
                         C_DIM * N_ID * (int)sizeof(float));
    fused_kernel<<<288, 256, C_DIM * N_ID * sizeof(float)>>>(hidden, bbox, outp);
}

// round 14
// speedup vs baseline: 2.8050x; 1.2047x over previous
#include <cuda_runtime.h>
#include <math.h>

#define C_DIM 1280
#define HW    9216
#define WIMG  96
#define N_ID  16
#define D_IN  512
#define B_SZ  8
#define M_ROWS 128
#define KCHUNK 8

// ---------------- scratch ----------------
__device__ float g_h[M_ROWS * C_DIM];
__device__ float g_part[KCHUNK * M_ROWS * C_DIM];
__device__ float g_pt[B_SZ * C_DIM * N_ID];    // projected [b][c][n]

// ---------------- f32x2 helpers ----------------
__device__ __forceinline__ unsigned long long fma2(unsigned long long a,
                                                   unsigned long long b,
                                                   unsigned long long c) {
    unsigned long long d;
    asm("fma.rn.f32x2 %0, %1, %2, %3;" : "=l"(d) : "l"(a), "l"(b), "l"(c));
    return d;
}
__device__ __forceinline__ unsigned long long packf2(float lo, float hi) {
    unsigned long long r;
    asm("mov.b64 %0, {%1, %2};" : "=l"(r) : "f"(lo), "f"(hi));
    return r;
}
__device__ __forceinline__ float2 unpackf2(unsigned long long v) {
    float2 r;
    asm("mov.b64 {%0, %1}, %2;" : "=f"(r.x), "=f"(r.y) : "l"(v));
    return r;
}

// ---------------- 32x64 tile GEMM core: 256 thr, 8 outputs/thread ----------------
// each thread: 2 rows x 4 cols.  tr = t>>4 (16 row-groups), tj = t&15 (16 col-groups)
template <bool GELU>
__device__ __forceinline__ void gemm32x64(const float* __restrict__ A, int ldA,
                                          const float* __restrict__ Wm,
                                          const float* __restrict__ bias,
                                          float* __restrict__ Out,
                                          int kt0, int ktEnd) {
    __shared__ float sAt[32][34];     // [k][row], stride 34 keeps u64 align
    __shared__ float sB[32][68];      // [k][col], stride 68 keeps float4 align
    int t = threadIdx.x;
    int tj = t & 15;
    int tr = t >> 4;
    int rowBase = blockIdx.y * 32;
    int colBase = blockIdx.x * 64;

    unsigned long long acc[2][2];
    acc[0][0] = acc[0][1] = acc[1][0] = acc[1][1] = 0ull;

    for (int kt = kt0; kt < ktEnd; kt += 32) {
#pragma unroll
        for (int s = 0; s < 4; s++) {          // A tile: 32 rows x 32 k
            int idx = t + s * 256;
            int row = idx >> 5, kk = idx & 31;
            sAt[kk][row] = A[(size_t)(rowBase + row) * ldA + kt + kk];
        }
#pragma unroll
        for (int s = 0; s < 8; s++) {          // B tile: 32 k x 64 cols
            int idx = t + s * 256;
            int r = idx >> 6, c = idx & 63;
            sB[r][c] = Wm[(size_t)(kt + r) * C_DIM + colBase + c];
        }
        __syncthreads();
#pragma unroll
        for (int k = 0; k < 32; k++) {
            float2 av = *(const float2*)&sAt[k][tr * 2];
            ulonglong2 bv = *(const ulonglong2*)&sB[k][tj * 4];
            unsigned long long a0 = packf2(av.x, av.x);
            unsigned long long a1 = packf2(av.y, av.y);
            acc[0][0] = fma2(a0, bv.x, acc[0][0]);
            acc[0][1] = fma2(a0, bv.y, acc[0][1]);
            acc[1][0] = fma2(a1, bv.x, acc[1][0]);
            acc[1][1] = fma2(a1, bv.y, acc[1][1]);
        }
        __syncthreads();
    }
#pragma unroll
    for (int r = 0; r < 2; r++) {
        float2 v0 = unpackf2(acc[r][0]);
        float2 v1 = unpackf2(acc[r][1]);
        float vals[4] = {v0.x, v0.y, v1.x, v1.y};
        int row = rowBase + tr * 2 + r;
        int col = colBase + tj * 4;
        float4 o;
        float* ov = (float*)&o;
#pragma unroll
        for (int i = 0; i < 4; i++) {
            float v = vals[i] + (bias ? bias[col + i] : 0.f);
            if (GELU) v = 0.5f * v * (1.f + erff(v * 0.70710678f));
            ov[i] = v;
        }
        *(float4*)&Out[(size_t)row * C_DIM + col] = o;
    }
}

// mlp1: grid (20, 4) = 80 CTAs, one clean wave
__global__ __launch_bounds__(256) void mlp1_kernel(const float* __restrict__ E,
                                                   const float* __restrict__ W1,
                                                   const float* __restrict__ b1) {
    gemm32x64<true>(E, D_IN, W1, b1, g_h, 0, D_IN);
}
// mlp2: split-K=8, grid (20, 4, 8) = 640 CTAs, balanced waves
__global__ __launch_bounds__(256) void mlp2_kernel(const float* __restrict__ W2) {
    int z = blockIdx.z;
    int kspan = C_DIM / KCHUNK;       // 160
    gemm32x64<false>(g_h, C_DIM, W2, nullptr,
                     g_part + (size_t)z * M_ROWS * C_DIM,
                     z * kspan, (z + 1) * kspan);
}

// ---------------- reduce split-K + bias + normalize -> g_pt[b][c][16] ----
__global__ __launch_bounds__(128) void norm_kernel(const float* __restrict__ b2v) {
    int r = blockIdx.x, t = threadIdx.x;
    int b = r >> 4, n = r & 15;
    float v[10];
    float ss = 0.f;
#pragma unroll
    for (int i = 0; i < 10; i++) {
        int c = t + i * 128;
        size_t o = (size_t)r * C_DIM + c;
        float x = b2v[c];
#pragma unroll
        for (int z = 0; z < KCHUNK; z++)
            x += g_part[o + (size_t)z * M_ROWS * C_DIM];
        v[i] = x;
        ss = fmaf(x, x, ss);
    }
#pragma unroll
    for (int o = 16; o > 0; o >>= 1) ss += __shfl_xor_sync(0xffffffffu, ss, o);
    __shared__ float sw[4];
    if ((t & 31) == 0) sw[t >> 5] = ss;
    __syncthreads();
    float tot = sw[0] + sw[1] + sw[2] + sw[3];
    float scale = 35.7770876f / (sqrtf(tot) + 1e-6f);
#pragma unroll
    for (int i = 0; i < 10; i++) {
        int c = t + i * 128;
        g_pt[((size_t)b * C_DIM + c) * N_ID + n] = v[i] * scale;
    }
}

// ---------------- fused main kernel (4-stage pipelined, 2 px/thread) ----------------
// 128 thr, 256 px/CTA, grid 288 (36 blk/batch), 80KB smem, 2 CTAs/SM
#define UNR 10         // channels per batch; 4 batches in flight, step 40; 1280 = 32*40
__global__ __launch_bounds__(128, 2) void fused_kernel(const float* __restrict__ hidden,
                                                       const float* __restrict__ bboxes,
                                                       float* __restrict__ out) {
    extern __shared__ float sp[];               // [1280][16]
    __shared__ int sx1[N_ID], sy1[N_ID], sx2[N_ID], sy2[N_ID], semp[N_ID];

    int t = threadIdx.x;
    int blk = blockIdx.x;
    int b = blk / 36;
    int px = (blk % 36) * 256 + 2 * t;          // even; pair never crosses a row

    const float4* src = (const float4*)(g_pt + (size_t)b * C_DIM * N_ID);
    float4* dst = (float4*)sp;
#pragma unroll
    for (int i = 0; i < 40; i++) dst[t + i * 128] = src[t + i * 128];

    if (t < N_ID) {
        float bx1 = bboxes[t * 4 + 0] * 96.f;
        float by1 = bboxes[t * 4 + 1] * 96.f;
        float bx2 = bboxes[t * 4 + 2] * 96.f;
        float by2 = bboxes[t * 4 + 3] * 96.f;
        int X1 = (int)floorf(fminf(fmaxf(bx1, 0.f), 96.f));
        int Y1 = (int)floorf(fminf(fmaxf(by1, 0.f), 96.f));
        int X2 = (int)floorf(fminf(fmaxf(bx2, 0.f), 96.f));
        int Y2 = (int)floorf(fminf(fmaxf(by2, 0.f), 96.f));
        sx1[t] = X1; sy1[t] = Y1; sx2[t] = X2; sy2[t] = Y2;
        semp[t] = (X1 >= X2) || (Y1 >= Y2);
    }
    __syncthreads();

    int allempty = 1;
#pragma unroll
    for (int n = 0; n < N_ID; n++) allempty &= semp[n];

    int y = px / WIMG;
    int x = px - y * WIMG;
    const float* hp = hidden + (size_t)b * C_DIM * HW + px;

    // ---- pass 1: sumsq + 16 dots for 2 px; 4-stage pipeline ----
    unsigned long long acc0[8], acc1[8];
#pragma unroll
    for (int k = 0; k < 8; k++) { acc0[k] = 0ull; acc1[k] = 0ull; }
    float ss0 = 0.f, ss1 = 0.f;

    float2 h0[UNR], h1[UNR], h2[UNR], h3[UNR];

#define LOADB(BUF, CB)                                                           \
    {                                                                            \
        _Pragma("unroll")                                                        \
        for (int i = 0; i < UNR; i++)                                            \
            BUF[i] = *(const float2*)(hp + (size_t)((CB) + i) * HW);             \
    }
#define LOADB_G(BUF, CB)                                                         \
    if ((CB) < C_DIM) LOADB(BUF, CB)

#define P1_COMPUTE(HBUF, CB)                                                     \
    {                                                                            \
        _Pragma("unroll")                                                        \
        for (int i = 0; i < UNR; i++) {                                          \
            ss0 = fmaf(HBUF[i].x, HBUF[i].x, ss0);                               \
            ss1 = fmaf(HBUF[i].y, HBUF[i].y, ss1);                               \
            unsigned long long hx = packf2(HBUF[i].x, HBUF[i].x);                \
            unsigned long long hy = packf2(HBUF[i].y, HBUF[i].y);                \
            const ulonglong2* p2 = (const ulonglong2*)(sp + (((CB) + i) << 4));  \
            ulonglong2 q0 = p2[0], q1 = p2[1], q2 = p2[2], q3 = p2[3];           \
            acc0[0] = fma2(hx, q0.x, acc0[0]);  acc1[0] = fma2(hy, q0.x, acc1[0]); \
            acc0[1] = fma2(hx, q0.y, acc0[1]);  acc1[1] = fma2(hy, q0.y, acc1[1]); \
            acc0[2] = fma2(hx, q1.x, acc0[2]);  acc1[2] = fma2(hy, q1.x, acc1[2]); \
            acc0[3] = fma2(hx, q1.y, acc0[3]);  acc1[3] = fma2(hy, q1.y, acc1[3]); \
            acc0[4] = fma2(hx, q2.x, acc0[4]);  acc1[4] = fma2(hy, q2.x, acc1[4]); \
            acc0[5] = fma2(hx, q2.y, acc0[5]);  acc1[5] = fma2(hy, q2.y, acc1[5]); \
            acc0[6] = fma2(hx, q3.x, acc0[6]);  acc1[6] = fma2(hy, q3.x, acc1[6]); \
            acc0[7] = fma2(hx, q3.y, acc0[7]);  acc1[7] = fma2(hy, q3.y, acc1[7]); \
        }                                                                        \
    }

    LOADB(h0, 0)
    LOADB(h1, UNR)
    LOADB(h2, 2 * UNR)
    for (int cb = 0; cb < C_DIM; cb += 4 * UNR) {
        LOADB(h3, cb + 3 * UNR)
        P1_COMPUTE(h0, cb)
        LOADB_G(h0, cb + 4 * UNR)
        P1_COMPUTE(h1, cb + UNR)
        LOADB_G(h1, cb + 5 * UNR)
        P1_COMPUTE(h2, cb + 2 * UNR)
        LOADB_G(h2, cb + 6 * UNR)
        P1_COMPUTE(h3, cb + 3 * UNR)
    }

    // ---- weights for both pixels ----
    const float invT = 1.999996f;               // 1/(0.5+1e-6)
    float inv0 = invT / (sqrtf(ss0) + 1e-6f);
    float inv1 = invT / (sqrtf(ss1) + 1e-6f);
    float w0[N_ID], w1[N_ID];
    float sum0 = 0.f, sum1 = 0.f;
#pragma unroll
    for (int k = 0; k < 8; k++) {
        float2 d0 = unpackf2(acc0[k]);
        float2 d1 = unpackf2(acc1[k]);
#pragma unroll
        for (int j = 0; j < 2; j++) {
            int n = 2 * k + j;
            float da = (j == 0) ? d0.x : d0.y;
            float db = (j == 0) ? d1.x : d1.y;
            int ybox = (y >= sy1[n]) & (y < sy2[n]);
            int m0 = allempty | (ybox & (x >= sx1[n]) & (x < sx2[n]));
            int m1 = allempty | (ybox & ((x + 1) >= sx1[n]) & ((x + 1) < sx2[n]));
            float s0 = 1.f / (1.f + __expf(-da * inv0));
            float s1 = 1.f / (1.f + __expf(-db * inv1));
            float wv0 = m0 ? s0 : 0.f;
            float wv1 = m1 ? s1 : 0.f;
            w0[n] = wv0; sum0 += wv0;
            w1[n] = wv1; sum1 += wv1;
        }
    }
    float is0 = 1.f / (sum0 + 1e-6f);
    float is1 = 1.f / (sum1 + 1e-6f);
    unsigned long long wp0[8], wp1[8];
#pragma unroll
    for (int k = 0; k < 8; k++) {
        wp0[k] = packf2(__powf(w0[2 * k] * is0, 1.2f), __powf(w0[2 * k + 1] * is0, 1.2f));
        wp1[k] = packf2(__powf(w1[2 * k] * is1, 1.2f), __powf(w1[2 * k + 1] * is1, 1.2f));
    }

    // ---- pass 2: out = hidden + 1.5*sum_n w[n]*p[n,c]; 4-stage pipeline ----
    float* op = out + (size_t)b * C_DIM * HW + px;

#define P2_COMPUTE(HBUF, CB)                                                     \
    {                                                                            \
        _Pragma("unroll")                                                        \
        for (int i = 0; i < UNR; i++) {                                          \
            const ulonglong2* pq = (const ulonglong2*)(sp + (((CB) + i) << 4));  \
            ulonglong2 q0 = pq[0], q1 = pq[1], q2 = pq[2], q3 = pq[3];           \
            unsigned long long s0 = 0ull, s1 = 0ull;                             \
            s0 = fma2(wp0[0], q0.x, s0);  s1 = fma2(wp1[0], q0.x, s1);           \
            s0 = fma2(wp0[1], q0.y, s0);  s1 = fma2(wp1[1], q0.y, s1);           \
            s0 = fma2(wp0[2], q1.x, s0);  s1 = fma2(wp1[2], q1.x, s1);           \
            s0 = fma2(wp0[3], q1.y, s0);  s1 = fma2(wp1[3], q1.y, s1);           \
            s0 = fma2(wp0[4], q2.x, s0);  s1 = fma2(wp1[4], q2.x, s1);           \
            s0 = fma2(wp0[5], q2.y, s0);  s1 = fma2(wp1[5], q2.y, s1);           \
            s0 = fma2(wp0[6], q3.x, s0);  s1 = fma2(wp1[6], q3.x, s1);           \
            s0 = fma2(wp0[7], q3.y, s0);  s1 = fma2(wp1[7], q3.y, s1);           \
            float2 a0 = unpackf2(s0), a1 = unpackf2(s1);                         \
            float2 o;                                                            \
            o.x = fmaf(1.5f, a0.x + a0.y, HBUF[i].x);                            \
            o.y = fmaf(1.5f, a1.x + a1.y, HBUF[i].y);                            \
            __stcs((float2*)(op + (size_t)((CB) + i) * HW), o);                  \
        }                                                                        \
    }

    LOADB(h0, 0)
    LOADB(h1, UNR)
    LOADB(h2, 2 * UNR)
    for (int cb = 0; cb < C_DIM; cb += 4 * UNR) {
        LOADB(h3, cb + 3 * UNR)
        P2_COMPUTE(h0, cb)
        LOADB_G(h0, cb + 4 * UNR)
        P2_COMPUTE(h1, cb + UNR)
        LOADB_G(h1, cb + 5 * UNR)
        P2_COMPUTE(h2, cb + 2 * UNR)
        LOADB_G(h2, cb + 6 * UNR)
        P2_COMPUTE(h3, cb + 3 * UNR)
    }
}

// ---------------- launch ----------------
extern "C" void kernel_launch(void* const* d_in, const int* in_sizes, int n_in,
                              void* d_out, int out_size) {
    const float* hidden = (const float*)d_in[0];
    const float* emb    = (const float*)d_in[1];
    const float* bbox   = (const float*)d_in[2];
    const float* W1     = (const float*)d_in[3];
    const float* b1v    = (const float*)d_in[4];
    const float* W2     = (const float*)d_in[5];
    const float* b2v    = (const float*)d_in[6];
    float* outp = (float*)d_out;

    mlp1_kernel<<<dim3(C_DIM / 64, M_ROWS / 32), 256>>>(emb, W1, b1v);
    mlp2_kernel<<<dim3(C_DIM / 64, M_ROWS / 32, KCHUNK), 256>>>(W2);
    norm_kernel<<<M_ROWS, 128>>>(b2v);

    cudaFuncSetAttribute(fused_kernel, cudaFuncAttributeMaxDynamicSharedMemorySize,
                         C_DIM * N_ID * (int)sizeof(float));
    fused_kernel<<<288, 128, C_DIM * N_ID * sizeof(float)>>>(hidden, bbox, outp);
}